// round 13
// baseline (speedup 1.0000x reference)
#include <cuda_runtime.h>

#define NB 32
#define NA 286
#define NAPB 288       // padded b (zero W rows 286..287)
#define CI 23
#define HH 100
#define KP 104         // padded k: 13 groups of 8 (zeros in pad)
#define NG 13
#define BPW 36         // b's per warp (288/8)
#define CH 6           // basis chunk per warp (6 chunks)

typedef unsigned long long ull;

__device__ __align__(16) float g_W[NB * NAPB * KP];  // feat@rW2^T, zero-padded
__device__ float g_c[NB * NA];
__device__ float g_part[NB * NA];
// per k-pair q (52): {c0p, c1p, c1p, c2p} — lane loads {c(s),c(s+1)} at +s*16
__device__ __align__(16) ull g_E[52 * 4];
__device__ __align__(16) ull g_cb[52];               // bias pairs

__device__ __forceinline__ ull pk2(float x, float y) {
    ull r; asm("mov.b64 %0, {%1,%2};" : "=l"(r) : "f"(x), "f"(y)); return r;
}
__device__ __forceinline__ ull dup2(float x) {
    ull r; asm("mov.b64 %0, {%1,%1};" : "=l"(r) : "f"(x)); return r;
}
__device__ __forceinline__ void unpk2(float& x, float& y, ull v) {
    asm("mov.b64 {%0,%1}, %2;" : "=f"(x), "=f"(y) : "l"(v));
}
__device__ __forceinline__ ull fma2(ull a, ull b, ull c) {
    ull d; asm("fma.rn.f32x2 %0, %1, %2, %3;" : "=l"(d) : "l"(a), "l"(b), "l"(c)); return d;
}
// packed relu via 2 scalar FMNMX (ALU pipe)
__device__ __forceinline__ ull relu2(ull v) {
    float a, b;
    asm("mov.b64 {%0,%1}, %2;" : "=f"(a), "=f"(b) : "l"(v));
    a = fmaxf(a, 0.f);
    b = fmaxf(b, 0.f);
    ull r; asm("mov.b64 %0, {%1,%2};" : "=l"(r) : "f"(a), "f"(b));
    return r;
}

// ---------------------------------------------------------------------------
// kA: g_W rows (zero-padded), g_c, tables g_E / g_cb.
// 576 blocks x 256 thr; block = (z = bx/18, 16 rows); warp handles 2 rows.
// ---------------------------------------------------------------------------
__global__ __launch_bounds__(256) void kA(const float* __restrict__ feat,
                                          const float* __restrict__ rW1,
                                          const float* __restrict__ rb1,
                                          const float* __restrict__ rW2,
                                          const float* __restrict__ rb2) {
    __shared__ float s_w2[HH * CI];
    __shared__ float s_f[8][2][24];
    int t = threadIdx.x, w = t >> 5, lane = t & 31;
    int bx = blockIdx.x;

    if (bx == 0 && t < 52) {             // tables, k-pad zeroed
        int k = 2 * t;
        float a0 = (k < HH) ? rW1[k] : 0.f;
        float a1 = (k + 1 < HH) ? rW1[k + 1] : 0.f;
        float b0 = (k < HH) ? rW1[HH + k] : 0.f;
        float b1 = (k + 1 < HH) ? rW1[HH + k + 1] : 0.f;
        float c0 = (k < HH) ? rW1[2 * HH + k] : 0.f;
        float c1 = (k + 1 < HH) ? rW1[2 * HH + k + 1] : 0.f;
        float d0 = (k < HH) ? rb1[k] : 0.f;
        float d1 = (k + 1 < HH) ? rb1[k + 1] : 0.f;
        ull c0p = pk2(a0, a1), c1p = pk2(b0, b1), c2p = pk2(c0, c1);
        g_E[t * 4 + 0] = c0p;
        g_E[t * 4 + 1] = c1p;
        g_E[t * 4 + 2] = c1p;
        g_E[t * 4 + 3] = c2p;
        g_cb[t] = pk2(d0, d1);
    }

    for (int i = t; i < HH * CI; i += 256) s_w2[i] = rW2[i];

    int z = bx / 18;
    int jb = (bx % 18) * 16 + w * 2;
    for (int i = 0; i < 2; i++) {
        int j = jb + i;
        if (j < NA && lane < CI) s_f[w][i][lane] = feat[(z * NA + j) * CI + lane];
    }
    __syncthreads();

    for (int i = 0; i < 2; i++) {
        int j = jb + i;
        float* Wr = g_W + (size_t)(z * NAPB + j) * KP;
        int k0 = lane, k1 = lane + 32, k2 = lane + 64, k3 = lane + 96;
        if (j < NA) {
            float a0 = 0.f, a1 = 0.f, a2 = 0.f, a3 = 0.f;
#pragma unroll
            for (int c = 0; c < CI; c++) {
                float fv = s_f[w][i][c];
                a0 = fmaf(fv, s_w2[k0 * CI + c], a0);
                a1 = fmaf(fv, s_w2[k1 * CI + c], a1);
                a2 = fmaf(fv, s_w2[k2 * CI + c], a2);
                if (k3 < HH) a3 = fmaf(fv, s_w2[k3 * CI + c], a3);
            }
            Wr[k0] = a0;
            Wr[k1] = a1;
            Wr[k2] = a2;
            if (k3 < KP) Wr[k3] = (k3 < HH) ? a3 : 0.f;
            if (lane == 0) {
                float cc = 0.f;
#pragma unroll
                for (int c = 0; c < CI; c++) cc = fmaf(rb2[c], s_f[w][i][c], cc);
                g_c[z * NA + j] = cc;
            }
        } else {
            Wr[k0] = 0.f; Wr[k1] = 0.f; Wr[k2] = 0.f;
            if (k3 < KP) Wr[k3] = 0.f;
        }
    }
}

// ---------------------------------------------------------------------------
// kB: block = (atile, z); 256 thr = 32 a-lanes x 8 b-warps.
// Per 2k: 2 dot-fma2 + relu2 (ALU) + acc-fma2 = 3 FMA-pipe ops.
// Segment selection by ADDRESS: lane LDG.128 at g_E + pair*32 + s*16.
// ---------------------------------------------------------------------------
__global__ __launch_bounds__(256, 2) void kB(const float* __restrict__ geom) {
    __shared__ float s_red[256];
    int t = threadIdx.x, al = t & 31, bl = t >> 5;
    int z = blockIdx.y, atile = blockIdx.x;
    int a = atile * 32 + al;
    bool valid = (a < NA);
    int ca = valid ? a : (NA - 1);

    const float* gp = geom + (size_t)z * NA * 3;
    float gax = gp[ca * 3 + 0];
    float gay = gp[ca * 3 + 1];
    float gaz = gp[ca * 3 + 2];

    const float* Wz = g_W + (size_t)z * NAPB * KP;
    const char* Ebase = (const char*)g_E;
    const ulonglong2* CB2 = (const ulonglong2*)g_cb;

    const float INV = 1.0f / 1.5f;
    const float PIO2 = 1.57079632679489662f;

    ull acc0 = 0ull, acc1 = 0ull, acc2 = 0ull, acc3 = 0ull;

    for (int c0 = 0; c0 < BPW; c0 += CH) {
        int bb = bl * BPW + c0;
        ull xlop[CH], xhip[CH];
        int eoff[CH];                      // s*16 byte offset into g_E pairs
#pragma unroll
        for (int i = 0; i < CH; i++) {
            int b = bb + i;
            int bc = (b < NA) ? b : (NA - 1);   // pad b: finite garbage, W row = 0
            float dx = gax - gp[bc * 3 + 0];
            float dy = gay - gp[bc * 3 + 1];
            float dz = gaz - gp[bc * 3 + 2];
            float d2 = fmaf(dx, dx, fmaf(dy, dy, fmaf(dz, dz, 1e-12f)));
            float r = d2 * rsqrtf(d2);
            bool s = (r >= 1.5f);
            float rr = s ? (r - 1.5f) : r;
            float ulo = __cosf(PIO2 * fminf(rr * INV, 1.f));
            float uhi = __cosf(PIO2 * fminf(rr * INV - 1.f, 1.f));
            xlop[i] = dup2(ulo);
            xhip[i] = dup2(uhi);
            eoff[i] = s ? 16 : 0;
        }
#pragma unroll 1
        for (int g = 0; g < NG; g++) {
            ulonglong2 cbA = CB2[g * 2 + 0];   // {cb pair0, cb pair1}
            ulonglong2 cbB = CB2[g * 2 + 1];   // {cb pair2, cb pair3}
            const char* Eg = Ebase + (size_t)g * 128;   // 4 pairs * 32B
            const float* Wp = Wz + (size_t)bb * KP + g * 8;
#pragma unroll
            for (int i = 0; i < CH; i++) {
                const ulonglong2* wr = (const ulonglong2*)(Wp + i * KP);
                ulonglong2 wlo = wr[0];   // k-pairs 0,1 of this group
                ulonglong2 whi = wr[1];   // k-pairs 2,3
                const char* Ei = Eg + eoff[i];
                ulonglong2 e0 = *(const ulonglong2*)(Ei + 0);    // {cA,cB} pair0
                ulonglong2 e1 = *(const ulonglong2*)(Ei + 32);   // pair1
                ulonglong2 e2 = *(const ulonglong2*)(Ei + 64);   // pair2
                ulonglong2 e3 = *(const ulonglong2*)(Ei + 96);   // pair3
                ull xl = xlop[i], xh = xhip[i];

                ull t0 = fma2(xh, e0.y, fma2(xl, e0.x, cbA.x));
                acc0 = fma2(relu2(t0), wlo.x, acc0);

                ull t1 = fma2(xh, e1.y, fma2(xl, e1.x, cbA.y));
                acc1 = fma2(relu2(t1), wlo.y, acc1);

                ull t2 = fma2(xh, e2.y, fma2(xl, e2.x, cbB.x));
                acc2 = fma2(relu2(t2), whi.x, acc2);

                ull t3 = fma2(xh, e3.y, fma2(xl, e3.x, cbB.y));
                acc3 = fma2(relu2(t3), whi.y, acc3);
            }
        }
    }

    float p0, p1, q0, q1, r0, r1, s0, s1;
    unpk2(p0, p1, acc0);
    unpk2(q0, q1, acc1);
    unpk2(r0, r1, acc2);
    unpk2(s0, s1, acc3);
    s_red[t] = ((p0 + p1) + (q0 + q1)) + ((r0 + r1) + (s0 + s1));
    __syncthreads();

    if (t < 32 && valid) {
        float s = 0.f;
#pragma unroll
        for (int l = 0; l < 8; l++) s += s_red[l * 32 + t];
        const float SCALE = 0.28209479177387814f / 16.911534525287763f;  // Y0/sqrt(N)
        g_part[(size_t)z * NA + a] = s * SCALE;
    }
}

// ---------------------------------------------------------------------------
// kC: csum = SCALE * sum_b c[z,b]; then MLP head 286 -> 30 -> 10 -> 1
// ---------------------------------------------------------------------------
__global__ __launch_bounds__(32) void kC(const float* __restrict__ fc1W,
                                         const float* __restrict__ fc1b,
                                         const float* __restrict__ fc2W,
                                         const float* __restrict__ fc2b,
                                         const float* __restrict__ fc3W,
                                         const float* __restrict__ fc3b,
                                         float* __restrict__ out) {
    int z = blockIdx.x, t = threadIdx.x;
    __shared__ float s1[30], s2[10];

    float cs = 0.f;
    for (int i = t; i < NA; i += 32) cs += g_c[z * NA + i];
#pragma unroll
    for (int o = 16; o > 0; o >>= 1) cs += __shfl_xor_sync(0xffffffffu, cs, o);
    const float SCALE = 0.28209479177387814f / 16.911534525287763f;
    cs *= SCALE;

    const float* p = g_part + (size_t)z * NA;
    if (t < 30) {
        float acc = fc1b[t];
#pragma unroll 4
        for (int i = 0; i < NA; i++)
            acc = fmaf(p[i] + cs, fc1W[i * 30 + t], acc);
        s1[t] = fmaxf(acc, 0.f);
    }
    __syncthreads();
    if (t < 10) {
        float acc = fc2b[t];
#pragma unroll
        for (int i = 0; i < 30; i++)
            acc = fmaf(s1[i], fc2W[i * 10 + t], acc);
        s2[t] = fmaxf(acc, 0.f);
    }
    __syncthreads();
    if (t == 0) {
        float acc = fc3b[0];
#pragma unroll
        for (int i = 0; i < 10; i++)
            acc = fmaf(s2[i], fc3W[i], acc);
        out[z] = acc;
    }
}

// ---------------------------------------------------------------------------
extern "C" void kernel_launch(void* const* d_in, const int* in_sizes, int n_in,
                              void* d_out, int out_size) {
    const float* features = (const float*)d_in[1];
    const float* geometry = (const float*)d_in[2];
    const float* rW1  = (const float*)d_in[3];
    const float* rb1  = (const float*)d_in[4];
    const float* rW2  = (const float*)d_in[5];
    const float* rb2  = (const float*)d_in[6];
    const float* fc1W = (const float*)d_in[7];
    const float* fc1b = (const float*)d_in[8];
    const float* fc2W = (const float*)d_in[9];
    const float* fc2b = (const float*)d_in[10];
    const float* fc3W = (const float*)d_in[11];
    const float* fc3b = (const float*)d_in[12];
    float* out = (float*)d_out;

    kA<<<576, 256>>>(features, rW1, rb1, rW2, rb2);
    dim3 gB(9, NB);
    kB<<<gB, 256>>>(geometry);
    kC<<<NB, 32>>>(fc1W, fc1b, fc2W, fc2b, fc3W, fc3b, out);
}

// round 14
// speedup vs baseline: 1.6052x; 1.6052x over previous
#include <cuda_runtime.h>

#define NB 32
#define NA 286
#define NAPB 288       // padded b (zero W rows 286..287)
#define CI 23
#define HH 100
#define KP 104         // padded k: 13 groups of 8 (zeros in pad)
#define NG 13
#define BPW 36         // b's per warp (288/8)
#define CH 6           // basis chunk per warp (6 chunks)

typedef unsigned long long ull;

__device__ __align__(16) float g_W[NB * NAPB * KP];  // feat@rW2^T, zero-padded
__device__ float g_c[NB * NA];
__device__ float g_part[NB * NA];
// per k-pair q (52): {c0p, c1p, c1p, c2p} — seg s reads 2 ulls at q*4 + s*2
__device__ __align__(16) ull g_E[52 * 4];
__device__ __align__(16) ull g_cb[52];               // bias pairs

__device__ __forceinline__ ull pk2(float x, float y) {
    ull r; asm("mov.b64 %0, {%1,%2};" : "=l"(r) : "f"(x), "f"(y)); return r;
}
__device__ __forceinline__ ull dup2(float x) {
    ull r; asm("mov.b64 %0, {%1,%1};" : "=l"(r) : "f"(x)); return r;
}
__device__ __forceinline__ void unpk2(float& x, float& y, ull v) {
    asm("mov.b64 {%0,%1}, %2;" : "=f"(x), "=f"(y) : "l"(v));
}
__device__ __forceinline__ ull fma2(ull a, ull b, ull c) {
    ull d; asm("fma.rn.f32x2 %0, %1, %2, %3;" : "=l"(d) : "l"(a), "l"(b), "l"(c)); return d;
}
// packed relu via 2 scalar FMNMX (ALU pipe)
__device__ __forceinline__ ull relu2(ull v) {
    float a, b;
    asm("mov.b64 {%0,%1}, %2;" : "=f"(a), "=f"(b) : "l"(v));
    a = fmaxf(a, 0.f);
    b = fmaxf(b, 0.f);
    ull r; asm("mov.b64 %0, {%1,%2};" : "=l"(r) : "f"(a), "f"(b));
    return r;
}

// ---------------------------------------------------------------------------
// kA: thread = k (weights in registers), 32 rows/block staged in SMEM.
// 288 blocks x 128 thr; block = (z = bx/9, rows j0..j0+31). Also builds
// g_E / g_cb (block 0) and g_c (threads 104..127).
// ---------------------------------------------------------------------------
__global__ __launch_bounds__(128) void kA(const float* __restrict__ feat,
                                          const float* __restrict__ rW1,
                                          const float* __restrict__ rb1,
                                          const float* __restrict__ rW2,
                                          const float* __restrict__ rb2) {
    __shared__ float s_f[32][24];
    __shared__ float s_b2[CI];
    int t = threadIdx.x;
    int bx = blockIdx.x;

    if (bx == 0 && t < 52) {             // tables, k-pad zeroed
        int k = 2 * t;
        float a0 = (k < HH) ? rW1[k] : 0.f;
        float a1 = (k + 1 < HH) ? rW1[k + 1] : 0.f;
        float b0 = (k < HH) ? rW1[HH + k] : 0.f;
        float b1 = (k + 1 < HH) ? rW1[HH + k + 1] : 0.f;
        float c0 = (k < HH) ? rW1[2 * HH + k] : 0.f;
        float c1 = (k + 1 < HH) ? rW1[2 * HH + k + 1] : 0.f;
        float d0 = (k < HH) ? rb1[k] : 0.f;
        float d1 = (k + 1 < HH) ? rb1[k + 1] : 0.f;
        ull c0p = pk2(a0, a1), c1p = pk2(b0, b1), c2p = pk2(c0, c1);
        g_E[t * 4 + 0] = c0p;
        g_E[t * 4 + 1] = c1p;
        g_E[t * 4 + 2] = c1p;
        g_E[t * 4 + 3] = c2p;
        g_cb[t] = pk2(d0, d1);
    }

    int z = bx / 9;
    int j0 = (bx % 9) * 32;

    // per-thread weight registers (thread t = k)
    float w2r[CI];
    bool kv = (t < HH);
    if (kv) {
#pragma unroll
        for (int c = 0; c < CI; c++) w2r[c] = rW2[t * CI + c];
    }
    if (t < CI) s_b2[t] = rb2[t];

    // stage 32 rows of features (pad rows -> 0)
    for (int i = t; i < 32 * CI; i += 128) {
        int rr = i / CI, c = i % CI;
        int j = j0 + rr;
        s_f[rr][c] = (j < NA) ? feat[((size_t)z * NA + j) * CI + c] : 0.f;
    }
    __syncthreads();

    if (t < KP) {
        for (int rr = 0; rr < 32; rr += 2) {       // 2-row unroll for chain ILP
            float acc0 = 0.f, acc1 = 0.f;
            if (kv) {
#pragma unroll
                for (int c = 0; c < CI; c++) {
                    acc0 = fmaf(w2r[c], s_f[rr][c], acc0);
                    acc1 = fmaf(w2r[c], s_f[rr + 1][c], acc1);
                }
            }
            g_W[(size_t)(z * NAPB + j0 + rr) * KP + t] = acc0;
            g_W[(size_t)(z * NAPB + j0 + rr + 1) * KP + t] = acc1;
        }
    } else {                                       // threads 104..127: g_c
        for (int rr = t - 104; rr < 32; rr += 24) {
            int j = j0 + rr;
            if (j < NA) {
                float cc = 0.f;
#pragma unroll
                for (int c = 0; c < CI; c++) cc = fmaf(s_b2[c], s_f[rr][c], cc);
                g_c[(size_t)z * NA + j] = cc;
            }
        }
    }
}

// ---------------------------------------------------------------------------
// kB: block = (atile, z); 256 thr = 32 a-lanes x 8 b-warps.
// Per 2k: 2 dot-fma2 + relu2 (ALU) + acc-fma2 = 3 FMA-pipe ops.
// Segment select via SMEM: per-lane LDS.128 hitting 2 distinct 16B lines.
// ---------------------------------------------------------------------------
__global__ __launch_bounds__(256, 2) void kB(const float* __restrict__ geom) {
    __shared__ __align__(16) ull s_E[52 * 4];      // 1664 B
    __shared__ float s_red[256];
    int t = threadIdx.x, al = t & 31, bl = t >> 5;
    int z = blockIdx.y, atile = blockIdx.x;
    int a = atile * 32 + al;
    bool valid = (a < NA);
    int ca = valid ? a : (NA - 1);

    for (int i = t; i < 52 * 4; i += 256) s_E[i] = g_E[i];

    const float* gp = geom + (size_t)z * NA * 3;
    float gax = gp[ca * 3 + 0];
    float gay = gp[ca * 3 + 1];
    float gaz = gp[ca * 3 + 2];

    const float* Wz = g_W + (size_t)z * NAPB * KP;
    const ulonglong2* CB2 = (const ulonglong2*)g_cb;

    const float INV = 1.0f / 1.5f;
    const float PIO2 = 1.57079632679489662f;

    ull acc0 = 0ull, acc1 = 0ull, acc2 = 0ull, acc3 = 0ull;
    __syncthreads();

    for (int c0 = 0; c0 < BPW; c0 += CH) {
        int bb = bl * BPW + c0;
        ull xlop[CH], xhip[CH];
        int sidx[CH];                              // seg offset in ull units (0 or 2)
#pragma unroll
        for (int i = 0; i < CH; i++) {
            int b = bb + i;
            int bc = (b < NA) ? b : (NA - 1);      // pad b: finite garbage, W row = 0
            float dx = gax - gp[bc * 3 + 0];
            float dy = gay - gp[bc * 3 + 1];
            float dz = gaz - gp[bc * 3 + 2];
            float d2 = fmaf(dx, dx, fmaf(dy, dy, fmaf(dz, dz, 1e-12f)));
            float r = d2 * rsqrtf(d2);
            bool s = (r >= 1.5f);
            float rr = s ? (r - 1.5f) : r;
            float ulo = __cosf(PIO2 * fminf(rr * INV, 1.f));
            float uhi = __cosf(PIO2 * fminf(rr * INV - 1.f, 1.f));
            xlop[i] = dup2(ulo);
            xhip[i] = dup2(uhi);
            sidx[i] = s ? 2 : 0;
        }
#pragma unroll 1
        for (int g = 0; g < NG; g++) {
            ulonglong2 cbA = CB2[g * 2 + 0];       // uniform LDG: {cb p0, cb p1}
            ulonglong2 cbB = CB2[g * 2 + 1];       // {cb p2, cb p3}
            const float* Wp = Wz + (size_t)bb * KP + g * 8;
            const ull* Eg = s_E + g * 16;
#pragma unroll
            for (int i = 0; i < CH; i++) {
                const ulonglong2* wr = (const ulonglong2*)(Wp + i * KP);
                ulonglong2 wlo = wr[0];            // k-pairs 0,1 of this group
                ulonglong2 whi = wr[1];            // k-pairs 2,3
                const ull* Ei = Eg + sidx[i];      // per-lane SMEM select
                ulonglong2 e0 = *(const ulonglong2*)(Ei + 0);   // {cA,cB} pair0
                ulonglong2 e1 = *(const ulonglong2*)(Ei + 4);   // pair1
                ulonglong2 e2 = *(const ulonglong2*)(Ei + 8);   // pair2
                ulonglong2 e3 = *(const ulonglong2*)(Ei + 12);  // pair3
                ull xl = xlop[i], xh = xhip[i];

                ull t0 = fma2(xh, e0.y, fma2(xl, e0.x, cbA.x));
                acc0 = fma2(relu2(t0), wlo.x, acc0);

                ull t1 = fma2(xh, e1.y, fma2(xl, e1.x, cbA.y));
                acc1 = fma2(relu2(t1), wlo.y, acc1);

                ull t2 = fma2(xh, e2.y, fma2(xl, e2.x, cbB.x));
                acc2 = fma2(relu2(t2), whi.x, acc2);

                ull t3 = fma2(xh, e3.y, fma2(xl, e3.x, cbB.y));
                acc3 = fma2(relu2(t3), whi.y, acc3);
            }
        }
    }

    float p0, p1, q0, q1, r0, r1, s0, s1;
    unpk2(p0, p1, acc0);
    unpk2(q0, q1, acc1);
    unpk2(r0, r1, acc2);
    unpk2(s0, s1, acc3);
    s_red[t] = ((p0 + p1) + (q0 + q1)) + ((r0 + r1) + (s0 + s1));
    __syncthreads();

    if (t < 32 && valid) {
        float s = 0.f;
#pragma unroll
        for (int l = 0; l < 8; l++) s += s_red[l * 32 + t];
        const float SCALE = 0.28209479177387814f / 16.911534525287763f;  // Y0/sqrt(N)
        g_part[(size_t)z * NA + a] = s * SCALE;
    }
}

// ---------------------------------------------------------------------------
// kC: csum = SCALE * sum_b c[z,b]; then MLP head 286 -> 30 -> 10 -> 1
// ---------------------------------------------------------------------------
__global__ __launch_bounds__(32) void kC(const float* __restrict__ fc1W,
                                         const float* __restrict__ fc1b,
                                         const float* __restrict__ fc2W,
                                         const float* __restrict__ fc2b,
                                         const float* __restrict__ fc3W,
                                         const float* __restrict__ fc3b,
                                         float* __restrict__ out) {
    int z = blockIdx.x, t = threadIdx.x;
    __shared__ float s1[30], s2[10];

    float cs = 0.f;
    for (int i = t; i < NA; i += 32) cs += g_c[z * NA + i];
#pragma unroll
    for (int o = 16; o > 0; o >>= 1) cs += __shfl_xor_sync(0xffffffffu, cs, o);
    const float SCALE = 0.28209479177387814f / 16.911534525287763f;
    cs *= SCALE;

    const float* p = g_part + (size_t)z * NA;
    if (t < 30) {
        float acc = fc1b[t];
#pragma unroll 4
        for (int i = 0; i < NA; i++)
            acc = fmaf(p[i] + cs, fc1W[i * 30 + t], acc);
        s1[t] = fmaxf(acc, 0.f);
    }
    __syncthreads();
    if (t < 10) {
        float acc = fc2b[t];
#pragma unroll
        for (int i = 0; i < 30; i++)
            acc = fmaf(s1[i], fc2W[i * 10 + t], acc);
        s2[t] = fmaxf(acc, 0.f);
    }
    __syncthreads();
    if (t == 0) {
        float acc = fc3b[0];
#pragma unroll
        for (int i = 0; i < 10; i++)
            acc = fmaf(s2[i], fc3W[i], acc);
        out[z] = acc;
    }
}

// ---------------------------------------------------------------------------
extern "C" void kernel_launch(void* const* d_in, const int* in_sizes, int n_in,
                              void* d_out, int out_size) {
    const float* features = (const float*)d_in[1];
    const float* geometry = (const float*)d_in[2];
    const float* rW1  = (const float*)d_in[3];
    const float* rb1  = (const float*)d_in[4];
    const float* rW2  = (const float*)d_in[5];
    const float* rb2  = (const float*)d_in[6];
    const float* fc1W = (const float*)d_in[7];
    const float* fc1b = (const float*)d_in[8];
    const float* fc2W = (const float*)d_in[9];
    const float* fc2b = (const float*)d_in[10];
    const float* fc3W = (const float*)d_in[11];
    const float* fc3b = (const float*)d_in[12];
    float* out = (float*)d_out;

    kA<<<288, 128>>>(features, rW1, rb1, rW2, rb2);
    dim3 gB(9, NB);
    kB<<<gB, 256>>>(geometry);
    kC<<<NB, 32>>>(fc1W, fc1b, fc2W, fc2b, fc3W, fc3b, out);
}